// round 10
// baseline (speedup 1.0000x reference)
#include <cuda_runtime.h>
#include <cstdint>

#define NMAX 100000
#define EPSV 1e-5f
#define KTAN 2.885390081777927f   // 2*log2(e)

typedef unsigned long long ull;

// 16 floats per node: [0..7] = b0 + x@W0_top, [8..15] = x@W0_bot
__device__ float g_nodefeat[NMAX * 16];
__device__ int g_idx_is64;
__device__ __align__(16) float g_staging[208];

// constant params: W1@0, W2@64, b1@128, g1@136, K*be1@144,
//   b2@152, g2@160, K*be2@168, W3@176, g0@184, K*be0@192, b3@200
__constant__ __align__(16) float c_p[208];

// ---------------- f32x2 / MUFU helpers ----------------
__device__ __forceinline__ ull pk2(float lo, float hi) {
    ull d; asm("mov.b64 %0, {%1, %2};" : "=l"(d) : "f"(lo), "f"(hi)); return d;
}
__device__ __forceinline__ ull pkdup(float v) {
    ull d; asm("mov.b64 %0, {%1, %1};" : "=l"(d) : "f"(v)); return d;
}
__device__ __forceinline__ void upk(ull v, float& lo, float& hi) {
    asm("mov.b64 {%0, %1}, %2;" : "=f"(lo), "=f"(hi) : "l"(v));
}
__device__ __forceinline__ ull add2(ull a, ull b) {
    ull d; asm("add.rn.f32x2 %0, %1, %2;" : "=l"(d) : "l"(a), "l"(b)); return d;
}
__device__ __forceinline__ ull mul2(ull a, ull b) {
    ull d; asm("mul.rn.f32x2 %0, %1, %2;" : "=l"(d) : "l"(a), "l"(b)); return d;
}
__device__ __forceinline__ ull fma2(ull a, ull b, ull c) {
    ull d; asm("fma.rn.f32x2 %0, %1, %2, %3;" : "=l"(d) : "l"(a), "l"(b), "l"(c)); return d;
}
__device__ __forceinline__ float ex2f_(float x) {
    float r; asm("ex2.approx.f32 %0, %1;" : "=f"(r) : "f"(x)); return r;
}
__device__ __forceinline__ float rcpf_(float x) {
    float r; asm("rcp.approx.f32 %0, %1;" : "=f"(r) : "f"(x)); return r;
}
__device__ __forceinline__ float rsqf_(float x) {
    float r; asm("rsqrt.approx.f32 %0, %1;" : "=f"(r) : "f"(x)); return r;
}
__device__ __forceinline__ ull shfl_xor_ull(ull v) {
    float a, b; upk(v, a, b);
    a = __shfl_xor_sync(0xffffffffu, a, 1);
    b = __shfl_xor_sync(0xffffffffu, b, 1);
    return pk2(a, b);
}
__device__ __forceinline__ ull sel_ull(bool p, ull a, ull b) { return p ? a : b; }

// ---------------- math blocks (params via direct 64-bit constant loads) ------

// LayerNorm over 8 packed values -> tanh -> 8 scalars.
// Emits y = tanh(ln(h)): LN output is pre-scaled by KTAN (folded into sc and
// the K*be constants), then tanh(x) = 1 - 2*rcp(ex2(u)+1).
template<int GOFF, int BOFF>
__device__ __forceinline__ void lnth8(const ull h[4], float y[8]) {
    ull s = add2(add2(h[0], h[1]), add2(h[2], h[3]));
    float sl, sh; upk(s, sl, sh);
    float m = (sl + sh) * 0.125f;

    ull q = mul2(h[0], h[0]);
    q = fma2(h[1], h[1], q);
    q = fma2(h[2], h[2], q);
    q = fma2(h[3], h[3], q);
    float ql, qh; upk(q, ql, qh);
    float msq = (ql + qh) * 0.125f;
    float var = fmaf(-m, m, msq);
    float sc = KTAN * rsqf_(var + EPSV);

    ull sc2 = pkdup(sc);
    ull nm2 = pkdup(-m);
    const ull* gp = reinterpret_cast<const ull*>(&c_p[GOFF]);
    const ull* bp = reinterpret_cast<const ull*>(&c_p[BOFF]);
#pragma unroll
    for (int p = 0; p < 4; p++) {
        ull ag = mul2(sc2, gp[p]);        // K*s*g
        ull c  = fma2(nm2, ag, bp[p]);    // K*be - m*K*s*g
        ull r  = fma2(h[p], ag, c);       // K*ln(h)
        float u0, u1; upk(r, u0, u1);
        float t0 = ex2f_(u0), t1 = ex2f_(u1);
        float r0 = rcpf_(t0 + 1.0f), r1 = rcpf_(t1 + 1.0f);
        y[2 * p]     = fmaf(-2.0f, r0, 1.0f);
        y[2 * p + 1] = fmaf(-2.0f, r1, 1.0f);
    }
}

// Quad-edge 8x8 matmul + bias; each weight constant load feeds 4 edges.
template<int WOFF, int BOFF>
__device__ __forceinline__ void mm8s4(const float y0[8], const float y1[8],
                                      const float y2[8], const float y3[8],
                                      ull o0[4], ull o1[4], ull o2[4], ull o3[4]) {
    const ull* bp = reinterpret_cast<const ull*>(&c_p[BOFF]);
#pragma unroll
    for (int p = 0; p < 4; p++) {
        ull b = bp[p];
        o0[p] = b; o1[p] = b; o2[p] = b; o3[p] = b;
    }
#pragma unroll
    for (int k = 0; k < 8; k++) {
        const ull* wr = reinterpret_cast<const ull*>(&c_p[WOFF + 8 * k]);
        ull w0 = wr[0], w1 = wr[1], w2 = wr[2], w3 = wr[3];
        ull h0 = pkdup(y0[k]), h1 = pkdup(y1[k]);
        ull h2 = pkdup(y2[k]), h3 = pkdup(y3[k]);
        o0[0] = fma2(h0, w0, o0[0]);  o1[0] = fma2(h1, w0, o1[0]);
        o2[0] = fma2(h2, w0, o2[0]);  o3[0] = fma2(h3, w0, o3[0]);
        o0[1] = fma2(h0, w1, o0[1]);  o1[1] = fma2(h1, w1, o1[1]);
        o2[1] = fma2(h2, w1, o2[1]);  o3[1] = fma2(h3, w1, o3[1]);
        o0[2] = fma2(h0, w2, o0[2]);  o1[2] = fma2(h1, w2, o1[2]);
        o2[2] = fma2(h2, w2, o2[2]);  o3[2] = fma2(h3, w2, o3[2]);
        o0[3] = fma2(h0, w3, o0[3]);  o1[3] = fma2(h1, w3, o1[3]);
        o2[3] = fma2(h2, w3, o2[3]);  o3[3] = fma2(h3, w3, o3[3]);
    }
}

// ---------------- kernel 1: node precompute + dtype detect + param staging ----
__global__ void node_prep(const float* __restrict__ x, const float* __restrict__ W0,
                          const float* __restrict__ b0, const void* __restrict__ ei,
                          const float* __restrict__ W1, const float* __restrict__ b1,
                          const float* __restrict__ g1, const float* __restrict__ be1,
                          const float* __restrict__ W2, const float* __restrict__ b2,
                          const float* __restrict__ g2, const float* __restrict__ be2,
                          const float* __restrict__ W3, const float* __restrict__ b3,
                          const float* __restrict__ g0, const float* __restrict__ be0,
                          int N) {
    __shared__ int s_ok;
    if (blockIdx.x == 0) {
        if (threadIdx.x == 0) s_ok = 1;
        __syncthreads();
        long long v = ((const long long*)ei)[threadIdx.x];
        if (v < 0 || v >= (long long)N) s_ok = 0;   // benign race: all write 0
        __syncthreads();
        if (threadIdx.x == 0) g_idx_is64 = s_ok;
    } else if (blockIdx.x == 1) {
        int t = threadIdx.x;
        if (t < 64) {
            g_staging[t] = W1[t];
        } else if (t < 128) {
            g_staging[t] = W2[t - 64];
        } else if (t < 208) {
            int i = t - 128, grp = i >> 3, j = i & 7;
            float v;
            switch (grp) {
                case 0: v = b1[j];          break;
                case 1: v = g1[j];          break;
                case 2: v = KTAN * be1[j];  break;
                case 3: v = b2[j];          break;
                case 4: v = g2[j];          break;
                case 5: v = KTAN * be2[j];  break;
                case 6: v = W3[j];          break;
                case 7: v = g0[j];          break;
                case 8: v = KTAN * be0[j];  break;
                default: v = (j == 0) ? b3[0] : 0.0f; break;
            }
            g_staging[128 + i] = v;
        }
    }

    int n = blockIdx.x * blockDim.x + threadIdx.x;
    if (n >= N) return;
    float x0 = x[n * 3 + 0], x1 = x[n * 3 + 1], x2 = x[n * 3 + 2];
    float t[16];
#pragma unroll
    for (int j = 0; j < 8; j++) {
        t[j]     = b0[j] + x0 * W0[j] + x1 * W0[8 + j] + x2 * W0[16 + j];
        t[8 + j] =         x0 * W0[24 + j] + x1 * W0[32 + j] + x2 * W0[40 + j];
    }
    float4* dst = reinterpret_cast<float4*>(g_nodefeat + (size_t)n * 16);
#pragma unroll
    for (int q = 0; q < 4; q++)
        dst[q] = make_float4(t[4 * q], t[4 * q + 1], t[4 * q + 2], t[4 * q + 3]);
}

// ---------------- kernel 2: per-edge MLP, 4 edges/thread, pair-coop gather ----
// Lanes 2i and 2i+1 cooperate: each gather instruction targets pair-uniform
// 32B node regions, split 16B/16B by lane parity -> one 128B line per pair
// per instruction. No early returns: all shuffles execute on clamped indices.
__global__ __launch_bounds__(256)
void edge_kernel(const void* __restrict__ ei_raw, float* __restrict__ out, int E) {
    int t = blockIdx.x * blockDim.x + threadIdx.x;
    int par = threadIdx.x & 1;
    int e0 = 4 * t;
    int Em1 = E - 1;
    bool vec = (e0 + 3 < E) && ((E & 3) == 0);

    int s[4], d[4];
    if (g_idx_is64) {
        const long long* ei = (const long long*)ei_raw;
        if (vec) {
            longlong2 sa = reinterpret_cast<const longlong2*>(ei)[2 * t];
            longlong2 sb = reinterpret_cast<const longlong2*>(ei)[2 * t + 1];
            longlong2 da = *reinterpret_cast<const longlong2*>(ei + E + e0);
            longlong2 db = *reinterpret_cast<const longlong2*>(ei + E + e0 + 2);
            s[0] = (int)sa.x; s[1] = (int)sa.y; s[2] = (int)sb.x; s[3] = (int)sb.y;
            d[0] = (int)da.x; d[1] = (int)da.y; d[2] = (int)db.x; d[3] = (int)db.y;
        } else {
#pragma unroll
            for (int i = 0; i < 4; i++) {
                int ce = min(e0 + i, Em1);
                s[i] = (int)ei[ce];
                d[i] = (int)ei[E + ce];
            }
        }
    } else {
        const int* ei = (const int*)ei_raw;
        if (vec) {
            int4 sv = reinterpret_cast<const int4*>(ei)[t];
            int4 dv = *reinterpret_cast<const int4*>(ei + E + e0);
            s[0] = sv.x; s[1] = sv.y; s[2] = sv.z; s[3] = sv.w;
            d[0] = dv.x; d[1] = dv.y; d[2] = dv.z; d[3] = dv.w;
        } else {
#pragma unroll
            for (int i = 0; i < 4; i++) {
                int ce = min(e0 + i, Em1);
                s[i] = ei[ce];
                d[i] = ei[E + ce];
            }
        }
    }

    const unsigned m = 0xffffffffu;
    int sp[4], dp[4];
#pragma unroll
    for (int i = 0; i < 4; i++) {
        sp[i] = __shfl_xor_sync(m, s[i], 1);
        dp[i] = __shfl_xor_sync(m, d[i], 1);
    }

    const ulonglong2* nf = reinterpret_cast<const ulonglong2*>(g_nodefeat);
    float y0[8], y1[8], y2[8], y3[8];
    float* ys[4] = {y0, y1, y2, y3};

#pragma unroll
    for (int i = 0; i < 4; i++) {
        // pair-uniform region bases: even-lane's edge i, odd-lane's edge i
        int sE = par ? sp[i] : s[i];
        int dE = par ? dp[i] : d[i];
        int sO = par ? s[i]  : sp[i];
        int dO = par ? d[i]  : dp[i];

        // region = node*64B; top at +0, bot at +32; my 16B slice at +par*16
        ulonglong2 LsE = nf[4 * sE + par];
        ulonglong2 LdE = nf[4 * dE + 2 + par];
        ulonglong2 LsO = nf[4 * sO + par];
        ulonglong2 LdO = nf[4 * dO + 2 + par];

        // combine s-top + d-bot BEFORE exchange
        ull hE0 = add2(LsE.x, LdE.x), hE1 = add2(LsE.y, LdE.y);
        ull hO0 = add2(LsO.x, LdO.x), hO1 = add2(LsO.y, LdO.y);

        // exchange partner-par halves of MY edge
        ull ex0 = sel_ull(par, hE0, hO0), ex1 = sel_ull(par, hE1, hO1);
        ull r0 = shfl_xor_ull(ex0), r1 = shfl_xor_ull(ex1);

        ull h[4];
        h[0] = sel_ull(par, r0, hE0);  h[1] = sel_ull(par, r1, hE1);
        h[2] = sel_ull(par, hO0, r0);  h[3] = sel_ull(par, hO1, r1);

        lnth8<184, 192>(h, ys[i]);     // g0, K*be0
    }

    ull p0[4], p1[4], p2[4], p3[4];
    mm8s4<0, 128>(y0, y1, y2, y3, p0, p1, p2, p3);     // W1, b1
    lnth8<136, 144>(p0, y0);  lnth8<136, 144>(p1, y1); // g1, K*be1
    lnth8<136, 144>(p2, y2);  lnth8<136, 144>(p3, y3);

    mm8s4<64, 152>(y0, y1, y2, y3, p0, p1, p2, p3);    // W2, b2
    lnth8<160, 168>(p0, y0);  lnth8<160, 168>(p1, y1); // g2, K*be2
    lnth8<160, 168>(p2, y2);  lnth8<160, 168>(p3, y3);

    float b3v = c_p[200];
    float a0 = b3v, a1 = b3v, a2 = b3v, a3 = b3v;
#pragma unroll
    for (int i = 0; i < 8; i++) {
        float w = c_p[176 + i];
        a0 = fmaf(y0[i], w, a0);
        a1 = fmaf(y1[i], w, a1);
        a2 = fmaf(y2[i], w, a2);
        a3 = fmaf(y3[i], w, a3);
    }
    if (vec) {
        *reinterpret_cast<float4*>(out + e0) = make_float4(a0, a1, a2, a3);
    } else {
        if (e0 < E)     out[e0] = a0;
        if (e0 + 1 < E) out[e0 + 1] = a1;
        if (e0 + 2 < E) out[e0 + 2] = a2;
        if (e0 + 3 < E) out[e0 + 3] = a3;
    }
}

// ---------------- launch ----------------
extern "C" void kernel_launch(void* const* d_in, const int* in_sizes, int n_in,
                              void* d_out, int out_size) {
    const float* x   = (const float*)d_in[0];
    const void*  ei  = (const void*)d_in[1];
    const float* W0  = (const float*)d_in[2];
    const float* b0  = (const float*)d_in[3];
    const float* g0  = (const float*)d_in[4];
    const float* be0 = (const float*)d_in[5];
    const float* W1  = (const float*)d_in[6];
    const float* b1  = (const float*)d_in[7];
    const float* g1  = (const float*)d_in[8];
    const float* be1 = (const float*)d_in[9];
    const float* W2  = (const float*)d_in[10];
    const float* b2  = (const float*)d_in[11];
    const float* g2  = (const float*)d_in[12];
    const float* be2 = (const float*)d_in[13];
    const float* W3  = (const float*)d_in[14];
    const float* b3  = (const float*)d_in[15];
    float* out = (float*)d_out;

    int N = in_sizes[0] / 3;
    if (N > NMAX) N = NMAX;
    int E = in_sizes[1] / 2;

    int nblocks = (N + 255) / 256;
    if (nblocks < 2) nblocks = 2;
    node_prep<<<nblocks, 256>>>(x, W0, b0, ei, W1, b1, g1, be1,
                                W2, b2, g2, be2, W3, b3, g0, be0, N);

    void* staging_ptr = nullptr;
    cudaGetSymbolAddress(&staging_ptr, g_staging);
    cudaMemcpyToSymbolAsync(c_p, staging_ptr, 208 * sizeof(float), 0,
                            cudaMemcpyDeviceToDevice);

    int threads = (E + 3) / 4;
    edge_kernel<<<(threads + 255) / 256, 256>>>(ei, out, E);
}

// round 11
// speedup vs baseline: 1.0740x; 1.0740x over previous
#include <cuda_runtime.h>
#include <cstdint>

#define NMAX 100000
#define EPSV 1e-5f
#define KTAN 2.885390081777927f   // 2*log2(e)

typedef unsigned long long ull;

// 16 floats per node: [0..7] = b0 + x@W0_top, [8..15] = x@W0_bot
__device__ float g_nodefeat[NMAX * 16];
__device__ int g_idx_is64;
__device__ __align__(16) float g_staging[208];

// constant params: W1@0, W2@64, b1@128, g1@136, K*be1@144,
//   b2@152, g2@160, K*be2@168, W3@176, g0@184, K*be0@192, b3@200
__constant__ __align__(16) float c_p[208];

// ---------------- f32x2 / MUFU helpers ----------------
__device__ __forceinline__ ull pk2(float lo, float hi) {
    ull d; asm("mov.b64 %0, {%1, %2};" : "=l"(d) : "f"(lo), "f"(hi)); return d;
}
__device__ __forceinline__ ull pkdup(float v) {
    ull d; asm("mov.b64 %0, {%1, %1};" : "=l"(d) : "f"(v)); return d;
}
__device__ __forceinline__ void upk(ull v, float& lo, float& hi) {
    asm("mov.b64 {%0, %1}, %2;" : "=f"(lo), "=f"(hi) : "l"(v));
}
__device__ __forceinline__ ull add2(ull a, ull b) {
    ull d; asm("add.rn.f32x2 %0, %1, %2;" : "=l"(d) : "l"(a), "l"(b)); return d;
}
__device__ __forceinline__ ull mul2(ull a, ull b) {
    ull d; asm("mul.rn.f32x2 %0, %1, %2;" : "=l"(d) : "l"(a), "l"(b)); return d;
}
__device__ __forceinline__ ull fma2(ull a, ull b, ull c) {
    ull d; asm("fma.rn.f32x2 %0, %1, %2, %3;" : "=l"(d) : "l"(a), "l"(b), "l"(c)); return d;
}
__device__ __forceinline__ float ex2f_(float x) {
    float r; asm("ex2.approx.f32 %0, %1;" : "=f"(r) : "f"(x)); return r;
}
__device__ __forceinline__ float rcpf_(float x) {
    float r; asm("rcp.approx.f32 %0, %1;" : "=f"(r) : "f"(x)); return r;
}
__device__ __forceinline__ float rsqf_(float x) {
    float r; asm("rsqrt.approx.f32 %0, %1;" : "=f"(r) : "f"(x)); return r;
}
__device__ __forceinline__ ull shfl_xor_ull(ull v) {
    float a, b; upk(v, a, b);
    a = __shfl_xor_sync(0xffffffffu, a, 1);
    b = __shfl_xor_sync(0xffffffffu, b, 1);
    return pk2(a, b);
}
__device__ __forceinline__ ull sel_ull(bool p, ull a, ull b) { return p ? a : b; }

// ---------------- math blocks (params via direct 64-bit constant loads) ------

// Fused LayerNorm -> tanh over 8 packed values, emitting 8 scalars.
// LN output pre-scaled by KTAN (folded into sc and the K*be constants),
// then tanh(x) = 1 - 2*rcp(ex2(u)+1).
template<int GOFF, int BOFF>
__device__ __forceinline__ void lnth8(const ull h[4], float y[8]) {
    ull s = add2(add2(h[0], h[1]), add2(h[2], h[3]));
    float sl, sh; upk(s, sl, sh);
    float m = (sl + sh) * 0.125f;

    ull q = mul2(h[0], h[0]);
    q = fma2(h[1], h[1], q);
    q = fma2(h[2], h[2], q);
    q = fma2(h[3], h[3], q);
    float ql, qh; upk(q, ql, qh);
    float msq = (ql + qh) * 0.125f;
    float var = fmaf(-m, m, msq);
    float sc = KTAN * rsqf_(var + EPSV);

    ull sc2 = pkdup(sc);
    ull nm2 = pkdup(-m);
    const ull* gp = reinterpret_cast<const ull*>(&c_p[GOFF]);
    const ull* bp = reinterpret_cast<const ull*>(&c_p[BOFF]);
#pragma unroll
    for (int p = 0; p < 4; p++) {
        ull ag = mul2(sc2, gp[p]);        // K*s*g
        ull c  = fma2(nm2, ag, bp[p]);    // K*be - m*K*s*g
        ull r  = fma2(h[p], ag, c);       // K*ln(h)
        float u0, u1; upk(r, u0, u1);
        float t0 = ex2f_(u0), t1 = ex2f_(u1);
        float r0 = rcpf_(t0 + 1.0f), r1 = rcpf_(t1 + 1.0f);
        y[2 * p]     = fmaf(-2.0f, r0, 1.0f);
        y[2 * p + 1] = fmaf(-2.0f, r1, 1.0f);
    }
}

// Dual-edge 8x8 matmul + bias; weights/biases via direct 64-bit constant loads.
template<int WOFF, int BOFF>
__device__ __forceinline__ void mm8s2(const float y0[8], const float y1[8],
                                      ull o0[4], ull o1[4]) {
    const ull* bp = reinterpret_cast<const ull*>(&c_p[BOFF]);
#pragma unroll
    for (int p = 0; p < 4; p++) {
        ull b = bp[p];
        o0[p] = b; o1[p] = b;
    }
#pragma unroll
    for (int k = 0; k < 8; k++) {
        const ull* wr = reinterpret_cast<const ull*>(&c_p[WOFF + 8 * k]);
        ull w0 = wr[0], w1 = wr[1], w2 = wr[2], w3 = wr[3];
        ull h0 = pkdup(y0[k]), h1 = pkdup(y1[k]);
        o0[0] = fma2(h0, w0, o0[0]);  o1[0] = fma2(h1, w0, o1[0]);
        o0[1] = fma2(h0, w1, o0[1]);  o1[1] = fma2(h1, w1, o1[1]);
        o0[2] = fma2(h0, w2, o0[2]);  o1[2] = fma2(h1, w2, o1[2]);
        o0[3] = fma2(h0, w3, o0[3]);  o1[3] = fma2(h1, w3, o1[3]);
    }
}

// ---------------- kernel 1: node precompute + dtype detect + param staging ----
__global__ void node_prep(const float* __restrict__ x, const float* __restrict__ W0,
                          const float* __restrict__ b0, const void* __restrict__ ei,
                          const float* __restrict__ W1, const float* __restrict__ b1,
                          const float* __restrict__ g1, const float* __restrict__ be1,
                          const float* __restrict__ W2, const float* __restrict__ b2,
                          const float* __restrict__ g2, const float* __restrict__ be2,
                          const float* __restrict__ W3, const float* __restrict__ b3,
                          const float* __restrict__ g0, const float* __restrict__ be0,
                          int N) {
    __shared__ int s_ok;
    if (blockIdx.x == 0) {
        if (threadIdx.x == 0) s_ok = 1;
        __syncthreads();
        long long v = ((const long long*)ei)[threadIdx.x];
        if (v < 0 || v >= (long long)N) s_ok = 0;   // benign race: all write 0
        __syncthreads();
        if (threadIdx.x == 0) g_idx_is64 = s_ok;
    } else if (blockIdx.x == 1) {
        int t = threadIdx.x;
        if (t < 64) {
            g_staging[t] = W1[t];
        } else if (t < 128) {
            g_staging[t] = W2[t - 64];
        } else if (t < 208) {
            int i = t - 128, grp = i >> 3, j = i & 7;
            float v;
            switch (grp) {
                case 0: v = b1[j];          break;
                case 1: v = g1[j];          break;
                case 2: v = KTAN * be1[j];  break;
                case 3: v = b2[j];          break;
                case 4: v = g2[j];          break;
                case 5: v = KTAN * be2[j];  break;
                case 6: v = W3[j];          break;
                case 7: v = g0[j];          break;
                case 8: v = KTAN * be0[j];  break;
                default: v = (j == 0) ? b3[0] : 0.0f; break;
            }
            g_staging[128 + i] = v;
        }
    }

    int n = blockIdx.x * blockDim.x + threadIdx.x;
    if (n >= N) return;
    float x0 = x[n * 3 + 0], x1 = x[n * 3 + 1], x2 = x[n * 3 + 2];
    float t[16];
#pragma unroll
    for (int j = 0; j < 8; j++) {
        t[j]     = b0[j] + x0 * W0[j] + x1 * W0[8 + j] + x2 * W0[16 + j];
        t[8 + j] =         x0 * W0[24 + j] + x1 * W0[32 + j] + x2 * W0[40 + j];
    }
    float4* dst = reinterpret_cast<float4*>(g_nodefeat + (size_t)n * 16);
#pragma unroll
    for (int q = 0; q < 4; q++)
        dst[q] = make_float4(t[4 * q], t[4 * q + 1], t[4 * q + 2], t[4 * q + 3]);
}

// ---------------- kernel 2: per-edge MLP, 2 edges/thread, pair-coop gather ----
// Lanes 2i and 2i+1 cooperate: each gather instruction targets ONE 32B node
// region per pair, split 16B/16B by lane parity -> one 128B line per pair
// per instruction (half the L1 wavefronts of the naive gather).
__global__ __launch_bounds__(256)
void edge_kernel(const void* __restrict__ ei_raw, float* __restrict__ out, int E) {
    int t = blockIdx.x * blockDim.x + threadIdx.x;
    int par = threadIdx.x & 1;
    int e0 = 2 * t, e1 = e0 + 1;
    int Em1 = E - 1;
    int ce0 = min(e0, Em1), ce1 = min(e1, Em1);

    int s0, d0, s1, d1;
    if (g_idx_is64) {
        const long long* ei = (const long long*)ei_raw;
        s0 = (int)ei[ce0];     s1 = (int)ei[ce1];
        d0 = (int)ei[E + ce0]; d1 = (int)ei[E + ce1];
    } else {
        const int* ei = (const int*)ei_raw;
        s0 = ei[ce0];     s1 = ei[ce1];
        d0 = ei[E + ce0]; d1 = ei[E + ce1];
    }

    const unsigned m = 0xffffffffu;
    int s0p = __shfl_xor_sync(m, s0, 1), d0p = __shfl_xor_sync(m, d0, 1);
    int s1p = __shfl_xor_sync(m, s1, 1), d1p = __shfl_xor_sync(m, d1, 1);

    // pair-uniform region bases: even-lane's edges (A..D), odd-lane's (Ap..Dp)
    int A  = par ? s0p : s0;
    int B  = par ? d0p : d0;
    int C  = par ? s1p : s1;
    int D  = par ? d1p : d1;
    int Ap = par ? s0  : s0p;
    int Bp = par ? d0  : d0p;
    int Cp = par ? s1  : s1p;
    int Dp = par ? d1  : d1p;

    const ulonglong2* nf = reinterpret_cast<const ulonglong2*>(g_nodefeat);
    // region = node*64B; top half at +0, bot half at +32; my 16B slice at +par*16
    ulonglong2 L0 = nf[4 * A  + par];        // even-edge0 s-top slice
    ulonglong2 L1 = nf[4 * B  + 2 + par];    // even-edge0 d-bot slice
    ulonglong2 L2 = nf[4 * C  + par];        // even-edge1 s-top slice
    ulonglong2 L3 = nf[4 * D  + 2 + par];
    ulonglong2 L4 = nf[4 * Ap + par];        // odd-edge0 s-top slice
    ulonglong2 L5 = nf[4 * Bp + 2 + par];
    ulonglong2 L6 = nf[4 * Cp + par];
    ulonglong2 L7 = nf[4 * Dp + 2 + par];

    // combine top+bot BEFORE exchange (halves the shuffled data)
    ull hA0 = add2(L0.x, L1.x), hA1 = add2(L0.y, L1.y);   // even-edge0, my-par half
    ull hB0 = add2(L2.x, L3.x), hB1 = add2(L2.y, L3.y);   // even-edge1
    ull hC0 = add2(L4.x, L5.x), hC1 = add2(L4.y, L5.y);   // odd-edge0
    ull hD0 = add2(L6.x, L7.x), hD1 = add2(L6.y, L7.y);   // odd-edge1

    // exchange the halves that belong to the partner's edges
    ull ex0 = sel_ull(par, hA0, hC0), ex1 = sel_ull(par, hA1, hC1);
    ull ex2_ = sel_ull(par, hB0, hD0), ex3 = sel_ull(par, hB1, hD1);
    ull r0 = shfl_xor_ull(ex0), r1 = shfl_xor_ull(ex1);
    ull r2 = shfl_xor_ull(ex2_), r3 = shfl_xor_ull(ex3);

    // assemble full h for MY edges: [lo half (j0-3), hi half (j4-7)]
    ull h0[4], h1[4];
    h0[0] = sel_ull(par, r0, hA0);  h0[1] = sel_ull(par, r1, hA1);
    h0[2] = sel_ull(par, hC0, r0);  h0[3] = sel_ull(par, hC1, r1);
    h1[0] = sel_ull(par, r2, hB0);  h1[1] = sel_ull(par, r3, hB1);
    h1[2] = sel_ull(par, hD0, r2);  h1[3] = sel_ull(par, hD1, r3);

    float y0[8], y1[8];
    lnth8<184, 192>(h0, y0);  lnth8<184, 192>(h1, y1);   // g0, K*be0

    ull p0[4], p1[4];
    mm8s2<0, 128>(y0, y1, p0, p1);                       // W1, b1
    lnth8<136, 144>(p0, y0);  lnth8<136, 144>(p1, y1);   // g1, K*be1

    mm8s2<64, 152>(y0, y1, p0, p1);                      // W2, b2
    lnth8<160, 168>(p0, y0);  lnth8<160, 168>(p1, y1);   // g2, K*be2

    float acc0 = c_p[200], acc1 = c_p[200];              // b3
#pragma unroll
    for (int i = 0; i < 8; i++) {
        float w = c_p[176 + i];
        acc0 = fmaf(y0[i], w, acc0);
        acc1 = fmaf(y1[i], w, acc1);
    }
    if (e1 < E) {
        *reinterpret_cast<float2*>(out + e0) = make_float2(acc0, acc1);
    } else if (e0 < E) {
        out[e0] = acc0;
    }
}

// ---------------- launch ----------------
extern "C" void kernel_launch(void* const* d_in, const int* in_sizes, int n_in,
                              void* d_out, int out_size) {
    const float* x   = (const float*)d_in[0];
    const void*  ei  = (const void*)d_in[1];
    const float* W0  = (const float*)d_in[2];
    const float* b0  = (const float*)d_in[3];
    const float* g0  = (const float*)d_in[4];
    const float* be0 = (const float*)d_in[5];
    const float* W1  = (const float*)d_in[6];
    const float* b1  = (const float*)d_in[7];
    const float* g1  = (const float*)d_in[8];
    const float* be1 = (const float*)d_in[9];
    const float* W2  = (const float*)d_in[10];
    const float* b2  = (const float*)d_in[11];
    const float* g2  = (const float*)d_in[12];
    const float* be2 = (const float*)d_in[13];
    const float* W3  = (const float*)d_in[14];
    const float* b3  = (const float*)d_in[15];
    float* out = (float*)d_out;

    int N = in_sizes[0] / 3;
    if (N > NMAX) N = NMAX;
    int E = in_sizes[1] / 2;

    int nblocks = (N + 255) / 256;
    if (nblocks < 2) nblocks = 2;
    node_prep<<<nblocks, 256>>>(x, W0, b0, ei, W1, b1, g1, be1,
                                W2, b2, g2, be2, W3, b3, g0, be0, N);

    void* staging_ptr = nullptr;
    cudaGetSymbolAddress(&staging_ptr, g_staging);
    cudaMemcpyToSymbolAsync(c_p, staging_ptr, 208 * sizeof(float), 0,
                            cudaMemcpyDeviceToDevice);

    int threads = (E + 1) / 2;
    edge_kernel<<<(threads + 255) / 256, 256>>>(ei, out, E);
}

// round 12
// speedup vs baseline: 1.1046x; 1.0284x over previous
#include <cuda_runtime.h>
#include <cstdint>

#define NMAX 100000
#define EPSV 1e-5f
#define KTAN 2.885390081777927f   // 2*log2(e)

typedef unsigned long long ull;

// 16 floats per node: [0..7] = b0 + x@W0_top, [8..15] = x@W0_bot
__device__ float g_nodefeat[NMAX * 16];
__device__ int g_idx_is64;
__device__ int g_unit;            // 1 if all g==1 and all be==0
__device__ __align__(16) float g_staging[288];

// constant params (floats):
//   W1@0, W2@64, b1@128, g1@136, K*be1@144, b2@152, g2@160, K*be2@168,
//   W3@176, g0@184, K*be0@192, b3@200,
//   g0sw@208 (half-swapped), K*be0sw@216, W1sw@224 (rows k<->k^4)
__constant__ __align__(16) float c_p[288];

// ---------------- f32x2 / MUFU helpers ----------------
__device__ __forceinline__ ull pkdup(float v) {
    ull d; asm("mov.b64 %0, {%1, %1};" : "=l"(d) : "f"(v)); return d;
}
__device__ __forceinline__ void upk(ull v, float& lo, float& hi) {
    asm("mov.b64 {%0, %1}, %2;" : "=f"(lo), "=f"(hi) : "l"(v));
}
__device__ __forceinline__ ull add2(ull a, ull b) {
    ull d; asm("add.rn.f32x2 %0, %1, %2;" : "=l"(d) : "l"(a), "l"(b)); return d;
}
__device__ __forceinline__ ull mul2(ull a, ull b) {
    ull d; asm("mul.rn.f32x2 %0, %1, %2;" : "=l"(d) : "l"(a), "l"(b)); return d;
}
__device__ __forceinline__ ull fma2(ull a, ull b, ull c) {
    ull d; asm("fma.rn.f32x2 %0, %1, %2, %3;" : "=l"(d) : "l"(a), "l"(b), "l"(c)); return d;
}
__device__ __forceinline__ float ex2f_(float x) {
    float r; asm("ex2.approx.f32 %0, %1;" : "=f"(r) : "f"(x)); return r;
}
__device__ __forceinline__ float rcpf_(float x) {
    float r; asm("rcp.approx.f32 %0, %1;" : "=f"(r) : "f"(x)); return r;
}
__device__ __forceinline__ float rsqf_(float x) {
    float r; asm("rsqrt.approx.f32 %0, %1;" : "=f"(r) : "f"(x)); return r;
}
__device__ __forceinline__ ull shfl64(ull v) {
    return __shfl_xor_sync(0xffffffffu, v, 1);
}
__device__ __forceinline__ ull sel_ull(bool p, ull a, ull b) { return p ? a : b; }

// ---------------- LN -> tanh blocks ----------------

// Shared LN statistics: emits sck = K*rsqrt(var+eps) and m_neg = -mean.
__device__ __forceinline__ void ln_stats(const ull h[4], float& sck, float& m_neg) {
    ull s = add2(add2(h[0], h[1]), add2(h[2], h[3]));
    float sl, sh; upk(s, sl, sh);
    m_neg = (sl + sh) * (-0.125f);

    ull q = mul2(h[0], h[0]);
    q = fma2(h[1], h[1], q);
    q = fma2(h[2], h[2], q);
    q = fma2(h[3], h[3], q);
    float ql, qh; upk(q, ql, qh);
    float msq = (ql + qh) * 0.125f;
    float var = fmaf(-m_neg, m_neg, msq);   // msq - m^2
    sck = KTAN * rsqf_(var + EPSV);
}

__device__ __forceinline__ void tanh_pair(ull r, float& y0, float& y1) {
    float u0, u1; upk(r, u0, u1);
    float t0 = ex2f_(u0), t1 = ex2f_(u1);
    float r0 = rcpf_(t0 + 1.0f), r1 = rcpf_(t1 + 1.0f);
    y0 = fmaf(-2.0f, r0, 1.0f);
    y1 = fmaf(-2.0f, r1, 1.0f);
}

// Unit-affine LN (g==1, be==0): apply = h*sck + m_neg*sck. No constant loads.
__device__ __forceinline__ void lnth8_unit(const ull h[4], float y[8]) {
    float sck, m_neg;
    ln_stats(h, sck, m_neg);
    ull sck2 = pkdup(sck);
    ull cm2  = pkdup(m_neg * sck);
#pragma unroll
    for (int p = 0; p < 4; p++) {
        ull r = fma2(h[p], sck2, cm2);
        tanh_pair(r, y[2 * p], y[2 * p + 1]);
    }
}

// General LN with runtime g/Kbe pointers (constant space).
__device__ __forceinline__ void lnth8_dyn(const ull h[4], float y[8],
                                          const float* gp_, const float* bp_) {
    float sck, m_neg;
    ln_stats(h, sck, m_neg);
    ull sc2 = pkdup(sck);
    ull nm2 = pkdup(m_neg);
    const ull* gp = reinterpret_cast<const ull*>(gp_);
    const ull* bp = reinterpret_cast<const ull*>(bp_);
#pragma unroll
    for (int p = 0; p < 4; p++) {
        ull ag = mul2(sc2, gp[p]);        // K*s*g
        ull c  = fma2(nm2, ag, bp[p]);    // K*be - m*K*s*g
        ull r  = fma2(h[p], ag, c);       // K*ln(h)
        tanh_pair(r, y[2 * p], y[2 * p + 1]);
    }
}

// Dual-edge 8x8 matmul + bias; W/B via runtime constant-space pointers.
__device__ __forceinline__ void mm8s2_p(const float y0[8], const float y1[8],
                                        ull o0[4], ull o1[4],
                                        const float* W, const float* B) {
    const ull* bp = reinterpret_cast<const ull*>(B);
#pragma unroll
    for (int p = 0; p < 4; p++) {
        ull b = bp[p];
        o0[p] = b; o1[p] = b;
    }
#pragma unroll
    for (int k = 0; k < 8; k++) {
        const ull* wr = reinterpret_cast<const ull*>(W + 8 * k);
        ull w0 = wr[0], w1 = wr[1], w2 = wr[2], w3 = wr[3];
        ull h0 = pkdup(y0[k]), h1 = pkdup(y1[k]);
        o0[0] = fma2(h0, w0, o0[0]);  o1[0] = fma2(h1, w0, o1[0]);
        o0[1] = fma2(h0, w1, o0[1]);  o1[1] = fma2(h1, w1, o1[1]);
        o0[2] = fma2(h0, w2, o0[2]);  o1[2] = fma2(h1, w2, o1[2]);
        o0[3] = fma2(h0, w3, o0[3]);  o1[3] = fma2(h1, w3, o1[3]);
    }
}

// Full MLP for 2 edges. Odd lanes hold h half-swapped (local order); the
// swapped g0/be0 copies (general path) and row-swapped W1 copy absorb it.
// After mm1 the state is in global order for both parities.
template<bool UNIT>
__device__ __forceinline__ void mlp2(const ull h0[4], const ull h1[4], int par,
                                     float& a0, float& a1) {
    const float* w1p = c_p + (par ? 224 : 0);
    float y0[8], y1[8];
    if (UNIT) {
        lnth8_unit(h0, y0); lnth8_unit(h1, y1);
    } else {
        const float* gp = c_p + (par ? 208 : 184);
        const float* bp = c_p + (par ? 216 : 192);
        lnth8_dyn(h0, y0, gp, bp); lnth8_dyn(h1, y1, gp, bp);
    }
    ull p0[4], p1[4];
    mm8s2_p(y0, y1, p0, p1, w1p, c_p + 128);          // W1(sw), b1
    if (UNIT) {
        lnth8_unit(p0, y0); lnth8_unit(p1, y1);
    } else {
        lnth8_dyn(p0, y0, c_p + 136, c_p + 144);
        lnth8_dyn(p1, y1, c_p + 136, c_p + 144);
    }
    mm8s2_p(y0, y1, p0, p1, c_p + 64, c_p + 152);     // W2, b2
    if (UNIT) {
        lnth8_unit(p0, y0); lnth8_unit(p1, y1);
    } else {
        lnth8_dyn(p0, y0, c_p + 160, c_p + 168);
        lnth8_dyn(p1, y1, c_p + 160, c_p + 168);
    }
    a0 = c_p[200]; a1 = c_p[200];
#pragma unroll
    for (int i = 0; i < 8; i++) {
        float w = c_p[176 + i];
        a0 = fmaf(y0[i], w, a0);
        a1 = fmaf(y1[i], w, a1);
    }
}

// ---------------- kernel 1: node precompute + dtype detect + param staging ----
__global__ void node_prep(const float* __restrict__ x, const float* __restrict__ W0,
                          const float* __restrict__ b0, const void* __restrict__ ei,
                          const float* __restrict__ W1, const float* __restrict__ b1,
                          const float* __restrict__ g1, const float* __restrict__ be1,
                          const float* __restrict__ W2, const float* __restrict__ b2,
                          const float* __restrict__ g2, const float* __restrict__ be2,
                          const float* __restrict__ W3, const float* __restrict__ b3,
                          const float* __restrict__ g0, const float* __restrict__ be0,
                          int N) {
    __shared__ int s_flag;
    if (blockIdx.x == 0) {
        if (threadIdx.x == 0) s_flag = 1;
        __syncthreads();
        long long v = ((const long long*)ei)[threadIdx.x];
        if (v < 0 || v >= (long long)N) s_flag = 0;   // benign race
        __syncthreads();
        if (threadIdx.x == 0) g_idx_is64 = s_flag;
    } else if (blockIdx.x == 1) {
        if (threadIdx.x == 0) s_flag = 1;
        __syncthreads();
        int t = threadIdx.x;
        int bad = 0;
        if (t < 64) {
            g_staging[t] = W1[t];
        } else if (t < 128) {
            g_staging[t] = W2[t - 64];
        } else if (t < 208) {
            int i = t - 128, grp = i >> 3, j = i & 7;
            float v;
            switch (grp) {
                case 0: v = b1[j]; break;
                case 1: v = g1[j]; if (v != 1.0f) bad = 1; break;
                case 2: { float b = be1[j]; if (b != 0.0f) bad = 1; v = KTAN * b; } break;
                case 3: v = b2[j]; break;
                case 4: v = g2[j]; if (v != 1.0f) bad = 1; break;
                case 5: { float b = be2[j]; if (b != 0.0f) bad = 1; v = KTAN * b; } break;
                case 6: v = W3[j]; break;
                case 7: v = g0[j]; if (v != 1.0f) bad = 1; break;
                case 8: { float b = be0[j]; if (b != 0.0f) bad = 1; v = KTAN * b; } break;
                default: v = (j == 0) ? b3[0] : 0.0f; break;
            }
            g_staging[128 + i] = v;
        } else if (t < 216) {              // g0 half-swapped
            int j = t - 208;
            g_staging[t] = g0[j ^ 4];
        } else if (t < 224) {              // K*be0 half-swapped
            int j = t - 216;
            g_staging[t] = KTAN * be0[j ^ 4];
        } else {                           // W1 rows k<->k^4, rows 0..3 part
            int i = t - 224;
            g_staging[t] = W1[(((i >> 3) ^ 4) << 3) + (i & 7)];
        }
        if (bad) s_flag = 0;               // benign race
        __syncthreads();
        if (threadIdx.x == 0) g_unit = s_flag;
    } else if (blockIdx.x == 2 && threadIdx.x < 32) {
        int t = 256 + threadIdx.x;         // W1sw rows 4..7 part
        int i = t - 224;
        g_staging[t] = W1[(((i >> 3) ^ 4) << 3) + (i & 7)];
    }

    int n = blockIdx.x * blockDim.x + threadIdx.x;
    if (n >= N) return;
    float x0 = x[n * 3 + 0], x1 = x[n * 3 + 1], x2 = x[n * 3 + 2];
    float t[16];
#pragma unroll
    for (int j = 0; j < 8; j++) {
        t[j]     = b0[j] + x0 * W0[j] + x1 * W0[8 + j] + x2 * W0[16 + j];
        t[8 + j] =         x0 * W0[24 + j] + x1 * W0[32 + j] + x2 * W0[40 + j];
    }
    float4* dst = reinterpret_cast<float4*>(g_nodefeat + (size_t)n * 16);
#pragma unroll
    for (int q = 0; q < 4; q++)
        dst[q] = make_float4(t[4 * q], t[4 * q + 1], t[4 * q + 2], t[4 * q + 3]);
}

// ---------------- kernel 2: per-edge MLP, 2 edges/thread, pair-coop gather ----
// A lane pair covers pair-edges 4q..4q+3 (broadcast index loads -> identical
// pair-ordered index registers, zero SELs on addresses). Each gather targets
// one 32B region split 16B/16B by parity -> one 128B line per pair per instr.
// Odd lanes keep h half-swapped (local order); constants absorb it.
__global__ __launch_bounds__(256)
void edge_kernel(const void* __restrict__ ei_raw, float* __restrict__ out, int E) {
    int t = blockIdx.x * blockDim.x + threadIdx.x;
    int par = threadIdx.x & 1;
    int q4 = (t >> 1) << 2;          // pair base edge
    int e0 = 2 * t;                  // my first edge (= q4 + 2*par)
    int Em1 = E - 1;

    int s4[4], d4[4];
    if (g_idx_is64) {
        const long long* ei = (const long long*)ei_raw;
        if ((q4 + 3 < E) && ((E & 1) == 0)) {
            longlong2 a  = *reinterpret_cast<const longlong2*>(ei + q4);
            longlong2 b  = *reinterpret_cast<const longlong2*>(ei + q4 + 2);
            longlong2 c  = *reinterpret_cast<const longlong2*>(ei + E + q4);
            longlong2 dd = *reinterpret_cast<const longlong2*>(ei + E + q4 + 2);
            s4[0] = (int)a.x; s4[1] = (int)a.y; s4[2] = (int)b.x; s4[3] = (int)b.y;
            d4[0] = (int)c.x; d4[1] = (int)c.y; d4[2] = (int)dd.x; d4[3] = (int)dd.y;
        } else {
#pragma unroll
            for (int i = 0; i < 4; i++) {
                int ce = min(q4 + i, Em1);
                s4[i] = (int)ei[ce];
                d4[i] = (int)ei[E + ce];
            }
        }
    } else {
        const int* ei = (const int*)ei_raw;
        if ((q4 + 3 < E) && ((E & 3) == 0)) {
            int4 sv = *reinterpret_cast<const int4*>(ei + q4);
            int4 dv = *reinterpret_cast<const int4*>(ei + E + q4);
            s4[0] = sv.x; s4[1] = sv.y; s4[2] = sv.z; s4[3] = sv.w;
            d4[0] = dv.x; d4[1] = dv.y; d4[2] = dv.z; d4[3] = dv.w;
        } else {
#pragma unroll
            for (int i = 0; i < 4; i++) {
                int ce = min(q4 + i, Em1);
                s4[i] = ei[ce];
                d4[i] = ei[E + ce];
            }
        }
    }

    // pair-uniform gather: my-par 16B slice of each pair-edge's h
    const ulonglong2* nf = reinterpret_cast<const ulonglong2*>(g_nodefeat);
    ull hXa[4], hXb[4];
#pragma unroll
    for (int i = 0; i < 4; i++) {
        ulonglong2 Ls = nf[4 * s4[i] + par];        // s-top slice
        ulonglong2 Ld = nf[4 * d4[i] + 2 + par];    // d-bot slice
        hXa[i] = add2(Ls.x, Ld.x);
        hXb[i] = add2(Ls.y, Ld.y);
    }

    // exchange: send my halves of partner's edges, keep mine, receive theirs
    bool p = (par != 0);
    ull sendAa = sel_ull(p, hXa[0], hXa[2]), sendAb = sel_ull(p, hXb[0], hXb[2]);
    ull sendBa = sel_ull(p, hXa[1], hXa[3]), sendBb = sel_ull(p, hXb[1], hXb[3]);
    ull keepAa = sel_ull(p, hXa[2], hXa[0]), keepAb = sel_ull(p, hXb[2], hXb[0]);
    ull keepBa = sel_ull(p, hXa[3], hXa[1]), keepBb = sel_ull(p, hXb[3], hXb[1]);
    ull rAa = shfl64(sendAa), rAb = shfl64(sendAb);
    ull rBa = shfl64(sendBa), rBb = shfl64(sendBb);

    // local-order h: [my-par half, partner-par half] (odd lanes half-swapped)
    ull h0[4] = {keepAa, keepAb, rAa, rAb};
    ull h1[4] = {keepBa, keepBb, rBa, rBb};

    float a0, a1;
    if (g_unit) mlp2<true>(h0, h1, par, a0, a1);
    else        mlp2<false>(h0, h1, par, a0, a1);

    if (e0 + 1 < E && q4 + 3 < E) {
        *reinterpret_cast<float2*>(out + e0) = make_float2(a0, a1);
    } else {
        if (e0 < E)     out[e0] = a0;
        if (e0 + 1 < E) out[e0 + 1] = a1;
    }
}

// ---------------- launch ----------------
extern "C" void kernel_launch(void* const* d_in, const int* in_sizes, int n_in,
                              void* d_out, int out_size) {
    const float* x   = (const float*)d_in[0];
    const void*  ei  = (const void*)d_in[1];
    const float* W0  = (const float*)d_in[2];
    const float* b0  = (const float*)d_in[3];
    const float* g0  = (const float*)d_in[4];
    const float* be0 = (const float*)d_in[5];
    const float* W1  = (const float*)d_in[6];
    const float* b1  = (const float*)d_in[7];
    const float* g1  = (const float*)d_in[8];
    const float* be1 = (const float*)d_in[9];
    const float* W2  = (const float*)d_in[10];
    const float* b2  = (const float*)d_in[11];
    const float* g2  = (const float*)d_in[12];
    const float* be2 = (const float*)d_in[13];
    const float* W3  = (const float*)d_in[14];
    const float* b3  = (const float*)d_in[15];
    float* out = (float*)d_out;

    int N = in_sizes[0] / 3;
    if (N > NMAX) N = NMAX;
    int E = in_sizes[1] / 2;

    int nblocks = (N + 255) / 256;
    if (nblocks < 3) nblocks = 3;
    node_prep<<<nblocks, 256>>>(x, W0, b0, ei, W1, b1, g1, be1,
                                W2, b2, g2, be2, W3, b3, g0, be0, N);

    void* staging_ptr = nullptr;
    cudaGetSymbolAddress(&staging_ptr, g_staging);
    cudaMemcpyToSymbolAsync(c_p, staging_ptr, 288 * sizeof(float), 0,
                            cudaMemcpyDeviceToDevice);

    int threads = (E + 1) / 2;
    edge_kernel<<<(threads + 255) / 256, 256>>>(ei, out, E);
}

// round 13
// speedup vs baseline: 1.5232x; 1.3790x over previous
#include <cuda_runtime.h>
#include <cstdint>

#define NMAX 100000
#define EPSV 1e-5f

typedef unsigned long long ull;

// 16 floats per node: [0..7] = b0 + x@W0_top, [8..15] = x@W0_bot
__device__ float g_nodefeat[NMAX * 16];
__device__ int g_idx_is64;
__device__ int g_unit;            // 1 if all g==1 and all be==0
__device__ __align__(16) float g_staging[288];

// constant params (floats):
//   W1@0, W2@64, b1@128, g1@136, be1@144, b2@152, g2@160, be2@168,
//   W3@176, g0@184, be0@192, b3@200,
//   g0sw@208 (half-swapped), be0sw@216, W1sw@224 (rows k<->k^4)
__constant__ __align__(16) float c_p[288];

// ---------------- f32x2 / MUFU helpers ----------------
__device__ __forceinline__ ull pkdup(float v) {
    ull d; asm("mov.b64 %0, {%1, %1};" : "=l"(d) : "f"(v)); return d;
}
__device__ __forceinline__ void upk(ull v, float& lo, float& hi) {
    asm("mov.b64 {%0, %1}, %2;" : "=f"(lo), "=f"(hi) : "l"(v));
}
__device__ __forceinline__ ull add2(ull a, ull b) {
    ull d; asm("add.rn.f32x2 %0, %1, %2;" : "=l"(d) : "l"(a), "l"(b)); return d;
}
__device__ __forceinline__ ull mul2(ull a, ull b) {
    ull d; asm("mul.rn.f32x2 %0, %1, %2;" : "=l"(d) : "l"(a), "l"(b)); return d;
}
__device__ __forceinline__ ull fma2(ull a, ull b, ull c) {
    ull d; asm("fma.rn.f32x2 %0, %1, %2, %3;" : "=l"(d) : "l"(a), "l"(b), "l"(c)); return d;
}
__device__ __forceinline__ float tanhf_(float x) {
    float r; asm("tanh.approx.f32 %0, %1;" : "=f"(r) : "f"(x)); return r;
}
__device__ __forceinline__ float rsqf_(float x) {
    float r; asm("rsqrt.approx.f32 %0, %1;" : "=f"(r) : "f"(x)); return r;
}
__device__ __forceinline__ ull shfl64(ull v) {
    return __shfl_xor_sync(0xffffffffu, v, 1);
}
__device__ __forceinline__ ull sel_ull(bool p, ull a, ull b) { return p ? a : b; }

// ---------------- LN -> tanh blocks ----------------

// Shared LN statistics: emits sc = rsqrt(var+eps) and m_neg = -mean.
__device__ __forceinline__ void ln_stats(const ull h[4], float& sc, float& m_neg) {
    ull s = add2(add2(h[0], h[1]), add2(h[2], h[3]));
    float sl, sh; upk(s, sl, sh);
    m_neg = (sl + sh) * (-0.125f);

    ull q = mul2(h[0], h[0]);
    q = fma2(h[1], h[1], q);
    q = fma2(h[2], h[2], q);
    q = fma2(h[3], h[3], q);
    float ql, qh; upk(q, ql, qh);
    float msq = (ql + qh) * 0.125f;
    float var = fmaf(-m_neg, m_neg, msq);   // msq - m^2
    sc = rsqf_(var + EPSV);
}

__device__ __forceinline__ void tanh_pair(ull r, float& y0, float& y1) {
    float u0, u1; upk(r, u0, u1);
    y0 = tanhf_(u0);
    y1 = tanhf_(u1);
}

// Unit-affine LN (g==1, be==0): apply = h*sc + m_neg*sc. No constant loads.
__device__ __forceinline__ void lnth8_unit(const ull h[4], float y[8]) {
    float sc, m_neg;
    ln_stats(h, sc, m_neg);
    ull sc2 = pkdup(sc);
    ull cm2 = pkdup(m_neg * sc);
#pragma unroll
    for (int p = 0; p < 4; p++) {
        ull r = fma2(h[p], sc2, cm2);
        tanh_pair(r, y[2 * p], y[2 * p + 1]);
    }
}

// General LN with runtime g/be pointers (constant space).
__device__ __forceinline__ void lnth8_dyn(const ull h[4], float y[8],
                                          const float* gp_, const float* bp_) {
    float sc, m_neg;
    ln_stats(h, sc, m_neg);
    ull sc2 = pkdup(sc);
    ull nm2 = pkdup(m_neg);
    const ull* gp = reinterpret_cast<const ull*>(gp_);
    const ull* bp = reinterpret_cast<const ull*>(bp_);
#pragma unroll
    for (int p = 0; p < 4; p++) {
        ull ag = mul2(sc2, gp[p]);        // s*g
        ull c  = fma2(nm2, ag, bp[p]);    // be - m*s*g
        ull r  = fma2(h[p], ag, c);       // ln(h)
        tanh_pair(r, y[2 * p], y[2 * p + 1]);
    }
}

// Dual-edge 8x8 matmul + bias; W/B via runtime constant-space pointers.
__device__ __forceinline__ void mm8s2_p(const float y0[8], const float y1[8],
                                        ull o0[4], ull o1[4],
                                        const float* W, const float* B) {
    const ull* bp = reinterpret_cast<const ull*>(B);
#pragma unroll
    for (int p = 0; p < 4; p++) {
        ull b = bp[p];
        o0[p] = b; o1[p] = b;
    }
#pragma unroll
    for (int k = 0; k < 8; k++) {
        const ull* wr = reinterpret_cast<const ull*>(W + 8 * k);
        ull w0 = wr[0], w1 = wr[1], w2 = wr[2], w3 = wr[3];
        ull h0 = pkdup(y0[k]), h1 = pkdup(y1[k]);
        o0[0] = fma2(h0, w0, o0[0]);  o1[0] = fma2(h1, w0, o1[0]);
        o0[1] = fma2(h0, w1, o0[1]);  o1[1] = fma2(h1, w1, o1[1]);
        o0[2] = fma2(h0, w2, o0[2]);  o1[2] = fma2(h1, w2, o1[2]);
        o0[3] = fma2(h0, w3, o0[3]);  o1[3] = fma2(h1, w3, o1[3]);
    }
}

// Full MLP for 2 edges. Odd lanes hold h half-swapped (local order); the
// swapped g0/be0 copies (general path) and row-swapped W1 copy absorb it.
// After mm1 the state is in global order for both parities.
template<bool UNIT>
__device__ __forceinline__ void mlp2(const ull h0[4], const ull h1[4], int par,
                                     float& a0, float& a1) {
    const float* w1p = c_p + (par ? 224 : 0);
    float y0[8], y1[8];
    if (UNIT) {
        lnth8_unit(h0, y0); lnth8_unit(h1, y1);
    } else {
        const float* gp = c_p + (par ? 208 : 184);
        const float* bp = c_p + (par ? 216 : 192);
        lnth8_dyn(h0, y0, gp, bp); lnth8_dyn(h1, y1, gp, bp);
    }
    ull p0[4], p1[4];
    mm8s2_p(y0, y1, p0, p1, w1p, c_p + 128);          // W1(sw), b1
    if (UNIT) {
        lnth8_unit(p0, y0); lnth8_unit(p1, y1);
    } else {
        lnth8_dyn(p0, y0, c_p + 136, c_p + 144);
        lnth8_dyn(p1, y1, c_p + 136, c_p + 144);
    }
    mm8s2_p(y0, y1, p0, p1, c_p + 64, c_p + 152);     // W2, b2
    if (UNIT) {
        lnth8_unit(p0, y0); lnth8_unit(p1, y1);
    } else {
        lnth8_dyn(p0, y0, c_p + 160, c_p + 168);
        lnth8_dyn(p1, y1, c_p + 160, c_p + 168);
    }
    a0 = c_p[200]; a1 = c_p[200];
#pragma unroll
    for (int i = 0; i < 8; i++) {
        float w = c_p[176 + i];
        a0 = fmaf(y0[i], w, a0);
        a1 = fmaf(y1[i], w, a1);
    }
}

// ---------------- kernel 1: node precompute + dtype detect + param staging ----
__global__ void node_prep(const float* __restrict__ x, const float* __restrict__ W0,
                          const float* __restrict__ b0, const void* __restrict__ ei,
                          const float* __restrict__ W1, const float* __restrict__ b1,
                          const float* __restrict__ g1, const float* __restrict__ be1,
                          const float* __restrict__ W2, const float* __restrict__ b2,
                          const float* __restrict__ g2, const float* __restrict__ be2,
                          const float* __restrict__ W3, const float* __restrict__ b3,
                          const float* __restrict__ g0, const float* __restrict__ be0,
                          int N) {
    __shared__ int s_flag;
    if (blockIdx.x == 0) {
        if (threadIdx.x == 0) s_flag = 1;
        __syncthreads();
        long long v = ((const long long*)ei)[threadIdx.x];
        if (v < 0 || v >= (long long)N) s_flag = 0;   // benign race
        __syncthreads();
        if (threadIdx.x == 0) g_idx_is64 = s_flag;
    } else if (blockIdx.x == 1) {
        if (threadIdx.x == 0) s_flag = 1;
        __syncthreads();
        int t = threadIdx.x;
        int bad = 0;
        if (t < 64) {
            g_staging[t] = W1[t];
        } else if (t < 128) {
            g_staging[t] = W2[t - 64];
        } else if (t < 208) {
            int i = t - 128, grp = i >> 3, j = i & 7;
            float v;
            switch (grp) {
                case 0: v = b1[j]; break;
                case 1: v = g1[j]; if (v != 1.0f) bad = 1; break;
                case 2: v = be1[j]; if (v != 0.0f) bad = 1; break;
                case 3: v = b2[j]; break;
                case 4: v = g2[j]; if (v != 1.0f) bad = 1; break;
                case 5: v = be2[j]; if (v != 0.0f) bad = 1; break;
                case 6: v = W3[j]; break;
                case 7: v = g0[j]; if (v != 1.0f) bad = 1; break;
                case 8: v = be0[j]; if (v != 0.0f) bad = 1; break;
                default: v = (j == 0) ? b3[0] : 0.0f; break;
            }
            g_staging[128 + i] = v;
        } else if (t < 216) {              // g0 half-swapped
            int j = t - 208;
            g_staging[t] = g0[j ^ 4];
        } else if (t < 224) {              // be0 half-swapped
            int j = t - 216;
            g_staging[t] = be0[j ^ 4];
        } else {                           // W1 rows k<->k^4, rows 0..3 part
            int i = t - 224;
            g_staging[t] = W1[(((i >> 3) ^ 4) << 3) + (i & 7)];
        }
        if (bad) s_flag = 0;               // benign race
        __syncthreads();
        if (threadIdx.x == 0) g_unit = s_flag;
    } else if (blockIdx.x == 2 && threadIdx.x < 32) {
        int t = 256 + threadIdx.x;         // W1sw rows 4..7 part
        int i = t - 224;
        g_staging[t] = W1[(((i >> 3) ^ 4) << 3) + (i & 7)];
    }

    int n = blockIdx.x * blockDim.x + threadIdx.x;
    if (n >= N) return;
    float x0 = x[n * 3 + 0], x1 = x[n * 3 + 1], x2 = x[n * 3 + 2];
    float t[16];
#pragma unroll
    for (int j = 0; j < 8; j++) {
        t[j]     = b0[j] + x0 * W0[j] + x1 * W0[8 + j] + x2 * W0[16 + j];
        t[8 + j] =         x0 * W0[24 + j] + x1 * W0[32 + j] + x2 * W0[40 + j];
    }
    float4* dst = reinterpret_cast<float4*>(g_nodefeat + (size_t)n * 16);
#pragma unroll
    for (int q = 0; q < 4; q++)
        dst[q] = make_float4(t[4 * q], t[4 * q + 1], t[4 * q + 2], t[4 * q + 3]);
}

// ---------------- kernel 2: per-edge MLP, 2 edges/thread, pair-coop gather ----
// A lane pair covers pair-edges 4q..4q+3 (broadcast index loads -> identical
// pair-ordered index registers, zero SELs on addresses). Each gather targets
// one 32B region split 16B/16B by parity -> one 128B line per pair per instr.
// Odd lanes keep h half-swapped (local order); constants absorb it.
__global__ __launch_bounds__(256)
void edge_kernel(const void* __restrict__ ei_raw, float* __restrict__ out, int E) {
    int t = blockIdx.x * blockDim.x + threadIdx.x;
    int par = threadIdx.x & 1;
    int q4 = (t >> 1) << 2;          // pair base edge
    int e0 = 2 * t;                  // my first edge (= q4 + 2*par)
    int Em1 = E - 1;

    int s4[4], d4[4];
    if (g_idx_is64) {
        const long long* ei = (const long long*)ei_raw;
        if ((q4 + 3 < E) && ((E & 1) == 0)) {
            longlong2 a  = *reinterpret_cast<const longlong2*>(ei + q4);
            longlong2 b  = *reinterpret_cast<const longlong2*>(ei + q4 + 2);
            longlong2 c  = *reinterpret_cast<const longlong2*>(ei + E + q4);
            longlong2 dd = *reinterpret_cast<const longlong2*>(ei + E + q4 + 2);
            s4[0] = (int)a.x; s4[1] = (int)a.y; s4[2] = (int)b.x; s4[3] = (int)b.y;
            d4[0] = (int)c.x; d4[1] = (int)c.y; d4[2] = (int)dd.x; d4[3] = (int)dd.y;
        } else {
#pragma unroll
            for (int i = 0; i < 4; i++) {
                int ce = min(q4 + i, Em1);
                s4[i] = (int)ei[ce];
                d4[i] = (int)ei[E + ce];
            }
        }
    } else {
        const int* ei = (const int*)ei_raw;
        if ((q4 + 3 < E) && ((E & 3) == 0)) {
            int4 sv = *reinterpret_cast<const int4*>(ei + q4);
            int4 dv = *reinterpret_cast<const int4*>(ei + E + q4);
            s4[0] = sv.x; s4[1] = sv.y; s4[2] = sv.z; s4[3] = sv.w;
            d4[0] = dv.x; d4[1] = dv.y; d4[2] = dv.z; d4[3] = dv.w;
        } else {
#pragma unroll
            for (int i = 0; i < 4; i++) {
                int ce = min(q4 + i, Em1);
                s4[i] = ei[ce];
                d4[i] = ei[E + ce];
            }
        }
    }

    // pair-uniform gather: my-par 16B slice of each pair-edge's h
    const ulonglong2* nf = reinterpret_cast<const ulonglong2*>(g_nodefeat);
    ull hXa[4], hXb[4];
#pragma unroll
    for (int i = 0; i < 4; i++) {
        ulonglong2 Ls = nf[4 * s4[i] + par];        // s-top slice
        ulonglong2 Ld = nf[4 * d4[i] + 2 + par];    // d-bot slice
        hXa[i] = add2(Ls.x, Ld.x);
        hXb[i] = add2(Ls.y, Ld.y);
    }

    // exchange: send my halves of partner's edges, keep mine, receive theirs
    bool p = (par != 0);
    ull sendAa = sel_ull(p, hXa[0], hXa[2]), sendAb = sel_ull(p, hXb[0], hXb[2]);
    ull sendBa = sel_ull(p, hXa[1], hXa[3]), sendBb = sel_ull(p, hXb[1], hXb[3]);
    ull keepAa = sel_ull(p, hXa[2], hXa[0]), keepAb = sel_ull(p, hXb[2], hXb[0]);
    ull keepBa = sel_ull(p, hXa[3], hXa[1]), keepBb = sel_ull(p, hXb[3], hXb[1]);
    ull rAa = shfl64(sendAa), rAb = shfl64(sendAb);
    ull rBa = shfl64(sendBa), rBb = shfl64(sendBb);

    // local-order h: [my-par half, partner-par half] (odd lanes half-swapped)
    ull h0[4] = {keepAa, keepAb, rAa, rAb};
    ull h1[4] = {keepBa, keepBb, rBa, rBb};

    float a0, a1;
    if (g_unit) mlp2<true>(h0, h1, par, a0, a1);
    else        mlp2<false>(h0, h1, par, a0, a1);

    if (e0 + 1 < E && q4 + 3 < E) {
        *reinterpret_cast<float2*>(out + e0) = make_float2(a0, a1);
    } else {
        if (e0 < E)     out[e0] = a0;
        if (e0 + 1 < E) out[e0 + 1] = a1;
    }
}

// ---------------- launch ----------------
extern "C" void kernel_launch(void* const* d_in, const int* in_sizes, int n_in,
                              void* d_out, int out_size) {
    const float* x   = (const float*)d_in[0];
    const void*  ei  = (const void*)d_in[1];
    const float* W0  = (const float*)d_in[2];
    const float* b0  = (const float*)d_in[3];
    const float* g0  = (const float*)d_in[4];
    const float* be0 = (const float*)d_in[5];
    const float* W1  = (const float*)d_in[6];
    const float* b1  = (const float*)d_in[7];
    const float* g1  = (const float*)d_in[8];
    const float* be1 = (const float*)d_in[9];
    const float* W2  = (const float*)d_in[10];
    const float* b2  = (const float*)d_in[11];
    const float* g2  = (const float*)d_in[12];
    const float* be2 = (const float*)d_in[13];
    const float* W3  = (const float*)d_in[14];
    const float* b3  = (const float*)d_in[15];
    float* out = (float*)d_out;

    int N = in_sizes[0] / 3;
    if (N > NMAX) N = NMAX;
    int E = in_sizes[1] / 2;

    int nblocks = (N + 255) / 256;
    if (nblocks < 3) nblocks = 3;
    node_prep<<<nblocks, 256>>>(x, W0, b0, ei, W1, b1, g1, be1,
                                W2, b2, g2, be2, W3, b3, g0, be0, N);

    void* staging_ptr = nullptr;
    cudaGetSymbolAddress(&staging_ptr, g_staging);
    cudaMemcpyToSymbolAsync(c_p, staging_ptr, 288 * sizeof(float), 0,
                            cudaMemcpyDeviceToDevice);

    int threads = (E + 1) / 2;
    edge_kernel<<<(threads + 255) / 256, 256>>>(ei, out, E);
}

// round 14
// speedup vs baseline: 1.5946x; 1.0468x over previous
#include <cuda_runtime.h>
#include <cstdint>

#define NMAX 100000
#define EPSV 1e-5f

typedef unsigned long long ull;

// 16 floats per node: [0..7] = b0 + x@W0_top, [8..15] = x@W0_bot
__device__ float g_nodefeat[NMAX * 16];
__device__ int g_idx_is64;
__device__ int g_unit;            // 1 if all g==1 and all be==0
__device__ __align__(16) float g_staging[288];

// constant params (floats):
//   W1@0, W2@64, b1@128, g1@136, be1@144, b2@152, g2@160, be2@168,
//   W3@176, g0@184, be0@192, b3@200,
//   g0sw@208 (half-swapped), be0sw@216, W1sw@224 (rows k<->k^4)
__constant__ __align__(16) float c_p[288];

// ---------------- f32x2 / MUFU helpers ----------------
__device__ __forceinline__ ull pkdup(float v) {
    ull d; asm("mov.b64 %0, {%1, %1};" : "=l"(d) : "f"(v)); return d;
}
__device__ __forceinline__ void upk(ull v, float& lo, float& hi) {
    asm("mov.b64 {%0, %1}, %2;" : "=f"(lo), "=f"(hi) : "l"(v));
}
__device__ __forceinline__ ull add2(ull a, ull b) {
    ull d; asm("add.rn.f32x2 %0, %1, %2;" : "=l"(d) : "l"(a), "l"(b)); return d;
}
__device__ __forceinline__ ull mul2(ull a, ull b) {
    ull d; asm("mul.rn.f32x2 %0, %1, %2;" : "=l"(d) : "l"(a), "l"(b)); return d;
}
__device__ __forceinline__ ull fma2(ull a, ull b, ull c) {
    ull d; asm("fma.rn.f32x2 %0, %1, %2, %3;" : "=l"(d) : "l"(a), "l"(b), "l"(c)); return d;
}
__device__ __forceinline__ float tanhf_(float x) {
    float r; asm("tanh.approx.f32 %0, %1;" : "=f"(r) : "f"(x)); return r;
}
__device__ __forceinline__ float rsqf_(float x) {
    float r; asm("rsqrt.approx.f32 %0, %1;" : "=f"(r) : "f"(x)); return r;
}
__device__ __forceinline__ ull shfl64(ull v) {
    return __shfl_xor_sync(0xffffffffu, v, 1);
}
__device__ __forceinline__ ull sel_ull(bool p, ull a, ull b) { return p ? a : b; }

// ---------------- LN -> tanh blocks ----------------

// Shared LN statistics: emits sc = rsqrt(var+eps) and m_neg = -mean.
__device__ __forceinline__ void ln_stats(const ull h[4], float& sc, float& m_neg) {
    ull s = add2(add2(h[0], h[1]), add2(h[2], h[3]));
    float sl, sh; upk(s, sl, sh);
    m_neg = (sl + sh) * (-0.125f);

    ull q = mul2(h[0], h[0]);
    q = fma2(h[1], h[1], q);
    q = fma2(h[2], h[2], q);
    q = fma2(h[3], h[3], q);
    float ql, qh; upk(q, ql, qh);
    float msq = (ql + qh) * 0.125f;
    float var = fmaf(-m_neg, m_neg, msq);   // msq - m^2
    sc = rsqf_(var + EPSV);
}

__device__ __forceinline__ void tanh_pair(ull r, float& y0, float& y1) {
    float u0, u1; upk(r, u0, u1);
    y0 = tanhf_(u0);
    y1 = tanhf_(u1);
}

// Unit-affine LN (g==1, be==0): apply = h*sc + m_neg*sc. No constant loads.
__device__ __forceinline__ void lnth8_unit(const ull h[4], float y[8]) {
    float sc, m_neg;
    ln_stats(h, sc, m_neg);
    ull sc2 = pkdup(sc);
    ull cm2 = pkdup(m_neg * sc);
#pragma unroll
    for (int p = 0; p < 4; p++) {
        ull r = fma2(h[p], sc2, cm2);
        tanh_pair(r, y[2 * p], y[2 * p + 1]);
    }
}

// General LN with runtime g/be pointers (constant space).
__device__ __forceinline__ void lnth8_dyn(const ull h[4], float y[8],
                                          const float* gp_, const float* bp_) {
    float sc, m_neg;
    ln_stats(h, sc, m_neg);
    ull sc2 = pkdup(sc);
    ull nm2 = pkdup(m_neg);
    const ull* gp = reinterpret_cast<const ull*>(gp_);
    const ull* bp = reinterpret_cast<const ull*>(bp_);
#pragma unroll
    for (int p = 0; p < 4; p++) {
        ull ag = mul2(sc2, gp[p]);        // s*g
        ull c  = fma2(nm2, ag, bp[p]);    // be - m*s*g
        ull r  = fma2(h[p], ag, c);       // ln(h)
        tanh_pair(r, y[2 * p], y[2 * p + 1]);
    }
}

// Dual-edge 8x8 matmul + bias; W/B via runtime constant-space pointers.
__device__ __forceinline__ void mm8s2_p(const float y0[8], const float y1[8],
                                        ull o0[4], ull o1[4],
                                        const float* W, const float* B) {
    const ull* bp = reinterpret_cast<const ull*>(B);
#pragma unroll
    for (int p = 0; p < 4; p++) {
        ull b = bp[p];
        o0[p] = b; o1[p] = b;
    }
#pragma unroll
    for (int k = 0; k < 8; k++) {
        const ull* wr = reinterpret_cast<const ull*>(W + 8 * k);
        ull w0 = wr[0], w1 = wr[1], w2 = wr[2], w3 = wr[3];
        ull h0 = pkdup(y0[k]), h1 = pkdup(y1[k]);
        o0[0] = fma2(h0, w0, o0[0]);  o1[0] = fma2(h1, w0, o1[0]);
        o0[1] = fma2(h0, w1, o0[1]);  o1[1] = fma2(h1, w1, o1[1]);
        o0[2] = fma2(h0, w2, o0[2]);  o1[2] = fma2(h1, w2, o1[2]);
        o0[3] = fma2(h0, w3, o0[3]);  o1[3] = fma2(h1, w3, o1[3]);
    }
}

// Full MLP for 2 edges. Odd lanes hold h half-swapped (local order); the
// swapped g0/be0 copies (general path) and row-swapped W1 copy absorb it.
// After mm1 the state is in global order for both parities.
template<bool UNIT>
__device__ __forceinline__ void mlp2(const ull h0[4], const ull h1[4], int par,
                                     float& a0, float& a1) {
    const float* w1p = c_p + (par ? 224 : 0);
    float y0[8], y1[8];
    if (UNIT) {
        lnth8_unit(h0, y0); lnth8_unit(h1, y1);
    } else {
        const float* gp = c_p + (par ? 208 : 184);
        const float* bp = c_p + (par ? 216 : 192);
        lnth8_dyn(h0, y0, gp, bp); lnth8_dyn(h1, y1, gp, bp);
    }
    ull p0[4], p1[4];
    mm8s2_p(y0, y1, p0, p1, w1p, c_p + 128);          // W1(sw), b1
    if (UNIT) {
        lnth8_unit(p0, y0); lnth8_unit(p1, y1);
    } else {
        lnth8_dyn(p0, y0, c_p + 136, c_p + 144);
        lnth8_dyn(p1, y1, c_p + 136, c_p + 144);
    }
    mm8s2_p(y0, y1, p0, p1, c_p + 64, c_p + 152);     // W2, b2
    if (UNIT) {
        lnth8_unit(p0, y0); lnth8_unit(p1, y1);
    } else {
        lnth8_dyn(p0, y0, c_p + 160, c_p + 168);
        lnth8_dyn(p1, y1, c_p + 160, c_p + 168);
    }
    a0 = c_p[200]; a1 = c_p[200];
#pragma unroll
    for (int i = 0; i < 8; i++) {
        float w = c_p[176 + i];
        a0 = fmaf(y0[i], w, a0);
        a1 = fmaf(y1[i], w, a1);
    }
}

// ---------------- kernel 1: node precompute + dtype detect + param staging ----
__global__ void node_prep(const float* __restrict__ x, const float* __restrict__ W0,
                          const float* __restrict__ b0, const void* __restrict__ ei,
                          const float* __restrict__ W1, const float* __restrict__ b1,
                          const float* __restrict__ g1, const float* __restrict__ be1,
                          const float* __restrict__ W2, const float* __restrict__ b2,
                          const float* __restrict__ g2, const float* __restrict__ be2,
                          const float* __restrict__ W3, const float* __restrict__ b3,
                          const float* __restrict__ g0, const float* __restrict__ be0,
                          int N) {
    __shared__ int s_flag;
    if (blockIdx.x == 0) {
        if (threadIdx.x == 0) s_flag = 1;
        __syncthreads();
        long long v = ((const long long*)ei)[threadIdx.x];
        if (v < 0 || v >= (long long)N) s_flag = 0;   // benign race
        __syncthreads();
        if (threadIdx.x == 0) g_idx_is64 = s_flag;
    } else if (blockIdx.x == 1) {
        if (threadIdx.x == 0) s_flag = 1;
        __syncthreads();
        int t = threadIdx.x;
        int bad = 0;
        if (t < 64) {
            g_staging[t] = W1[t];
        } else if (t < 128) {
            g_staging[t] = W2[t - 64];
        } else if (t < 208) {
            int i = t - 128, grp = i >> 3, j = i & 7;
            float v;
            switch (grp) {
                case 0: v = b1[j]; break;
                case 1: v = g1[j]; if (v != 1.0f) bad = 1; break;
                case 2: v = be1[j]; if (v != 0.0f) bad = 1; break;
                case 3: v = b2[j]; break;
                case 4: v = g2[j]; if (v != 1.0f) bad = 1; break;
                case 5: v = be2[j]; if (v != 0.0f) bad = 1; break;
                case 6: v = W3[j]; break;
                case 7: v = g0[j]; if (v != 1.0f) bad = 1; break;
                case 8: v = be0[j]; if (v != 0.0f) bad = 1; break;
                default: v = (j == 0) ? b3[0] : 0.0f; break;
            }
            g_staging[128 + i] = v;
        } else if (t < 216) {              // g0 half-swapped
            int j = t - 208;
            g_staging[t] = g0[j ^ 4];
        } else if (t < 224) {              // be0 half-swapped
            int j = t - 216;
            g_staging[t] = be0[j ^ 4];
        } else {                           // W1 rows k<->k^4, rows 0..3 part
            int i = t - 224;
            g_staging[t] = W1[(((i >> 3) ^ 4) << 3) + (i & 7)];
        }
        if (bad) s_flag = 0;               // benign race
        __syncthreads();
        if (threadIdx.x == 0) g_unit = s_flag;
    } else if (blockIdx.x == 2 && threadIdx.x < 32) {
        int t = 256 + threadIdx.x;         // W1sw rows 4..7 part
        int i = t - 224;
        g_staging[t] = W1[(((i >> 3) ^ 4) << 3) + (i & 7)];
    }

    int n = blockIdx.x * blockDim.x + threadIdx.x;
    if (n >= N) return;
    float x0 = x[n * 3 + 0], x1 = x[n * 3 + 1], x2 = x[n * 3 + 2];
    float t[16];
#pragma unroll
    for (int j = 0; j < 8; j++) {
        t[j]     = b0[j] + x0 * W0[j] + x1 * W0[8 + j] + x2 * W0[16 + j];
        t[8 + j] =         x0 * W0[24 + j] + x1 * W0[32 + j] + x2 * W0[40 + j];
    }
    float4* dst = reinterpret_cast<float4*>(g_nodefeat + (size_t)n * 16);
#pragma unroll
    for (int q = 0; q < 4; q++)
        dst[q] = make_float4(t[4 * q], t[4 * q + 1], t[4 * q + 2], t[4 * q + 3]);
}

// ---------------- kernel 2: per-edge MLP, 2 edges/thread, pair-coop gather ----
// 128-thread blocks, 12 blocks/SM target: forces regs<=40 so 48 warps/SM fit
// (75% theoretical occupancy; latency-bound regime per R13 profile).
__global__ __launch_bounds__(128, 12)
void edge_kernel(const void* __restrict__ ei_raw, float* __restrict__ out, int E) {
    int t = blockIdx.x * blockDim.x + threadIdx.x;
    int par = threadIdx.x & 1;
    int q4 = (t >> 1) << 2;          // pair base edge
    int e0 = 2 * t;                  // my first edge (= q4 + 2*par)
    int Em1 = E - 1;

    int s4[4], d4[4];
    if (g_idx_is64) {
        const long long* ei = (const long long*)ei_raw;
        if ((q4 + 3 < E) && ((E & 1) == 0)) {
            longlong2 a  = *reinterpret_cast<const longlong2*>(ei + q4);
            longlong2 b  = *reinterpret_cast<const longlong2*>(ei + q4 + 2);
            longlong2 c  = *reinterpret_cast<const longlong2*>(ei + E + q4);
            longlong2 dd = *reinterpret_cast<const longlong2*>(ei + E + q4 + 2);
            s4[0] = (int)a.x; s4[1] = (int)a.y; s4[2] = (int)b.x; s4[3] = (int)b.y;
            d4[0] = (int)c.x; d4[1] = (int)c.y; d4[2] = (int)dd.x; d4[3] = (int)dd.y;
        } else {
#pragma unroll
            for (int i = 0; i < 4; i++) {
                int ce = min(q4 + i, Em1);
                s4[i] = (int)ei[ce];
                d4[i] = (int)ei[E + ce];
            }
        }
    } else {
        const int* ei = (const int*)ei_raw;
        if ((q4 + 3 < E) && ((E & 3) == 0)) {
            int4 sv = *reinterpret_cast<const int4*>(ei + q4);
            int4 dv = *reinterpret_cast<const int4*>(ei + E + q4);
            s4[0] = sv.x; s4[1] = sv.y; s4[2] = sv.z; s4[3] = sv.w;
            d4[0] = dv.x; d4[1] = dv.y; d4[2] = dv.z; d4[3] = dv.w;
        } else {
#pragma unroll
            for (int i = 0; i < 4; i++) {
                int ce = min(q4 + i, Em1);
                s4[i] = ei[ce];
                d4[i] = ei[E + ce];
            }
        }
    }

    // pair-uniform gather: my-par 16B slice of each pair-edge's h
    const ulonglong2* nf = reinterpret_cast<const ulonglong2*>(g_nodefeat);
    ull hXa[4], hXb[4];
#pragma unroll
    for (int i = 0; i < 4; i++) {
        ulonglong2 Ls = nf[4 * s4[i] + par];        // s-top slice
        ulonglong2 Ld = nf[4 * d4[i] + 2 + par];    // d-bot slice
        hXa[i] = add2(Ls.x, Ld.x);
        hXb[i] = add2(Ls.y, Ld.y);
    }

    // exchange: send my halves of partner's edges, keep mine, receive theirs
    bool p = (par != 0);
    ull sendAa = sel_ull(p, hXa[0], hXa[2]), sendAb = sel_ull(p, hXb[0], hXb[2]);
    ull sendBa = sel_ull(p, hXa[1], hXa[3]), sendBb = sel_ull(p, hXb[1], hXb[3]);
    ull keepAa = sel_ull(p, hXa[2], hXa[0]), keepAb = sel_ull(p, hXb[2], hXb[0]);
    ull keepBa = sel_ull(p, hXa[3], hXa[1]), keepBb = sel_ull(p, hXb[3], hXb[1]);
    ull rAa = shfl64(sendAa), rAb = shfl64(sendAb);
    ull rBa = shfl64(sendBa), rBb = shfl64(sendBb);

    // local-order h: [my-par half, partner-par half] (odd lanes half-swapped)
    ull h0[4] = {keepAa, keepAb, rAa, rAb};
    ull h1[4] = {keepBa, keepBb, rBa, rBb};

    float a0, a1;
    if (g_unit) mlp2<true>(h0, h1, par, a0, a1);
    else        mlp2<false>(h0, h1, par, a0, a1);

    if (e0 + 1 < E && q4 + 3 < E) {
        *reinterpret_cast<float2*>(out + e0) = make_float2(a0, a1);
    } else {
        if (e0 < E)     out[e0] = a0;
        if (e0 + 1 < E) out[e0 + 1] = a1;
    }
}

// ---------------- launch ----------------
extern "C" void kernel_launch(void* const* d_in, const int* in_sizes, int n_in,
                              void* d_out, int out_size) {
    const float* x   = (const float*)d_in[0];
    const void*  ei  = (const void*)d_in[1];
    const float* W0  = (const float*)d_in[2];
    const float* b0  = (const float*)d_in[3];
    const float* g0  = (const float*)d_in[4];
    const float* be0 = (const float*)d_in[5];
    const float* W1  = (const float*)d_in[6];
    const float* b1  = (const float*)d_in[7];
    const float* g1  = (const float*)d_in[8];
    const float* be1 = (const float*)d_in[9];
    const float* W2  = (const float*)d_in[10];
    const float* b2  = (const float*)d_in[11];
    const float* g2  = (const float*)d_in[12];
    const float* be2 = (const float*)d_in[13];
    const float* W3  = (const float*)d_in[14];
    const float* b3  = (const float*)d_in[15];
    float* out = (float*)d_out;

    int N = in_sizes[0] / 3;
    if (N > NMAX) N = NMAX;
    int E = in_sizes[1] / 2;

    int nblocks = (N + 255) / 256;
    if (nblocks < 3) nblocks = 3;
    node_prep<<<nblocks, 256>>>(x, W0, b0, ei, W1, b1, g1, be1,
                                W2, b2, g2, be2, W3, b3, g0, be0, N);

    void* staging_ptr = nullptr;
    cudaGetSymbolAddress(&staging_ptr, g_staging);
    cudaMemcpyToSymbolAsync(c_p, staging_ptr, 288 * sizeof(float), 0,
                            cudaMemcpyDeviceToDevice);

    int threads = (E + 1) / 2;
    edge_kernel<<<(threads + 127) / 128, 128>>>(ei, out, E);
}